// round 1
// baseline (speedup 1.0000x reference)
#include <cuda_runtime.h>

// Problem constants (fixed by the dataset: B=32, N=1024, D=32, k = N//5 = 204)
#define BB      32
#define NN      1024
#define DD      32
#define KSEL    204
#define THREADS 256
#define WARPS   8

// Output layout (float32 concat of x, edge_index, edge_attr_emb)
#define X_ELEMS   (BB * NN * DD)            // 1,048,576
#define E_EDGES   ((long)BB * NN * KSEL)    // 6,684,672
#define EI_OFF    ((long)X_ELEMS)
#define EA_OFF    (EI_OFF + 2 * E_EDGES)    // 14,417,920

// Shared layout (bytes): slocs 8KB | sdist 32KB | cand 16KB | W/b 256B
#define SMEM_BYTES (8192 + 32768 + 16384 + 256)

__global__ __launch_bounds__(THREADS, 3)
void edge_knn_kernel(const float2* __restrict__ locs,
                     const float*  __restrict__ emb,
                     const float*  __restrict__ Wv,
                     const float*  __restrict__ bv,
                     float*        __restrict__ out)
{
    extern __shared__ unsigned char smem[];
    float2*             slocs = (float2*)smem;                          // [1024]
    unsigned*           sdist = (unsigned*)(smem + 8192);               // [8][1024]
    unsigned long long* cand  = (unsigned long long*)(smem + 8192 + 32768); // [8][256]
    float*              sW    = (float*)(smem + 8192 + 32768 + 16384);  // [32]
    float*              sB    = sW + 32;                                // [32]

    const int tid  = threadIdx.x;
    const int lane = tid & 31;
    const int w    = tid >> 5;
    const int cta  = blockIdx.x;          // 4096 CTAs
    const int batch = cta >> 7;           // 128 CTAs per batch instance
    const int i0    = (cta & 127) << 3;   // 8 rows per CTA (one per warp)

    // ---- x copy: out[0 : 1,048,576] = init_embeddings (4096*256 == X_ELEMS) ----
    out[cta * THREADS + tid] = emb[cta * THREADS + tid];

    // ---- stage batch locs + W/b into shared ----
    #pragma unroll
    for (int t = tid; t < NN; t += THREADS)
        slocs[t] = locs[batch * NN + t];
    if (tid < 32)      sW[tid]      = Wv[tid];
    else if (tid < 64) sB[tid - 32] = bv[tid - 32];
    __syncthreads();

    // ================= per-warp: one row i =================
    const int i = i0 + w;
    const float2 mi = slocs[i];
    unsigned* dist = sdist + w * NN;
    unsigned long long* mycand = cand + w * 256;
    unsigned* hist = (unsigned*)mycand;   // alias: hist (1KB) lives inside cand (2KB)

    // zero hist
    #pragma unroll
    for (int r = 0; r < 8; ++r) hist[lane + 32 * r] = 0u;
    __syncwarp();

    // ---- pass 1: distances (bit-exact vs reference) + histogram ----
    // sq = dx*dx + dy*dy with NO fma contraction; sqrt correctly rounded.
    #pragma unroll 4
    for (int it = 0; it < NN / 32; ++it) {
        int j = it * 32 + lane;
        float2 lj = slocs[j];
        float dx = mi.x - lj.x;
        float dy = mi.y - lj.y;
        float sq = __fadd_rn(__fmul_rn(dx, dx), __fmul_rn(dy, dy));
        float d  = __fsqrt_rn(sq);
        unsigned bits = (j == i) ? 0x7F800000u : __float_as_uint(d);
        dist[j] = bits;
        if (j != i) {
            int bin = (int)(d * 180.0f);
            bin = bin > 255 ? 255 : bin;
            atomicAdd(&hist[bin], 1u);
        }
    }
    __syncwarp();

    // ---- threshold bin: first bin with cumulative count >= KSEL ----
    unsigned h[8];
    int lsum = 0;
    #pragma unroll
    for (int r = 0; r < 8; ++r) { h[r] = hist[lane * 8 + r]; lsum += (int)h[r]; }
    int incl = lsum;
    #pragma unroll
    for (int o = 1; o < 32; o <<= 1) {
        int v = __shfl_up_sync(0xFFFFFFFFu, incl, o);
        if (lane >= o) incl += v;
    }
    int c  = incl - lsum;   // exclusive prefix of this lane's 8 bins
    int tb = 256;
    #pragma unroll
    for (int r = 0; r < 8; ++r) {
        c += (int)h[r];
        if (c >= KSEL && tb == 256) tb = lane * 8 + r;
    }
    #pragma unroll
    for (int o = 16; o; o >>= 1) {
        int v = __shfl_xor_sync(0xFFFFFFFFu, tb, o);
        tb = v < tb ? v : tb;
    }
    __syncwarp();   // hist reads done; cand region may now be overwritten

    // ---- pass 2: compact candidates (bin <= tb) into cand, warp-aggregated ----
    int cnt = 0;
    #pragma unroll 4
    for (int it = 0; it < NN / 32; ++it) {
        int j = it * 32 + lane;
        unsigned bits = dist[j];
        bool take = false;
        if (bits < 0x7F800000u) {
            float d = __uint_as_float(bits);
            int bin = (int)(d * 180.0f);
            bin = bin > 255 ? 255 : bin;
            take = (bin <= tb);
        }
        unsigned m = __ballot_sync(0xFFFFFFFFu, take);
        int pos = cnt + __popc(m & ((1u << lane) - 1u));
        if (take && pos < 256)
            mycand[pos] = ((unsigned long long)bits << 32) | (unsigned)j;
        cnt += __popc(m);
    }
    int total = cnt > 256 ? 256 : cnt;    // cnt>256 statistically impossible here
    for (int p = total + lane; p < 256; p += 32)
        mycand[p] = ~0ULL;
    __syncwarp();

    // ---- register-resident bitonic sort of 256 u64 keys (8 per lane) ----
    // element e = r*32 + lane
    unsigned long long key[8];
    #pragma unroll
    for (int r = 0; r < 8; ++r) key[r] = mycand[r * 32 + lane];

    #pragma unroll
    for (int kl = 1; kl <= 8; ++kl) {
        #pragma unroll
        for (int sl = kl - 1; sl >= 0; --sl) {
            #pragma unroll
            for (int r = 0; r < 8; ++r) {
                bool up;
                if (kl >= 6)      up = ((r & (1 << (kl >= 6 ? kl - 5 : 0))) == 0);
                else if (kl == 5) up = ((r & 1) == 0);
                else              up = ((lane & (1 << kl)) == 0);
                if (sl >= 5) {
                    const int rs = 1 << (sl >= 5 ? sl - 5 : 0);
                    if ((r & rs) == 0) {
                        const int r2 = r + rs;
                        unsigned long long a = key[r], b2 = key[r2];
                        bool sw = up ? (a > b2) : (a < b2);
                        key[r]  = sw ? b2 : a;
                        key[r2] = sw ? a  : b2;
                    }
                } else {
                    const int s = 1 << sl;
                    unsigned long long other = __shfl_xor_sync(0xFFFFFFFFu, key[r], s);
                    bool keepMin = (((lane & s) == 0) == up);
                    bool less = key[r] < other;
                    unsigned long long mn = less ? key[r] : other;
                    unsigned long long mx = less ? other : key[r];
                    key[r] = keepMin ? mn : mx;
                }
            }
        }
    }

    // dump sorted keys back to shared for emission
    #pragma unroll
    for (int r = 0; r < 8; ++r) mycand[r * 32 + lane] = key[r];
    __syncwarp();

    // ---- emission ----
    const long  row  = (long)batch * NN + i;         // global node id
    float* o_src = out + EI_OFF;
    float* o_dst = o_src + E_EDGES;
    float* o_ea  = out + EA_OFF;
    const float srcv = (float)row;

    // edge_index (src row, dst row) as float32
    for (int kk = lane; kk < KSEL; kk += 32) {
        unsigned long long kv = mycand[kk];
        int j = (int)(unsigned)kv;
        o_src[row * KSEL + kk] = srcv;
        o_dst[row * KSEL + kk] = (float)((long)batch * NN + j);
    }

    // edge_attr_emb: out[e, c] = d * W[c] + b[c], float4-vectorized, coalesced
    const int eg = lane >> 3;          // which of 4 edges this lane covers
    const int c4 = (lane & 7) * 4;     // 4 embedding dims
    const float4 W4 = *(const float4*)(sW + c4);
    const float4 B4 = *(const float4*)(sB + c4);
    float* eabase = o_ea + row * (long)(KSEL * DD);
    #pragma unroll 4
    for (int kk0 = 0; kk0 < KSEL; kk0 += 4) {
        int kk = kk0 + eg;             // kk <= 203 always (204 = 4*51)
        unsigned dbits = *((unsigned*)&mycand[kk] + 1);   // high word = dist bits
        float d = __uint_as_float(dbits);
        float4 o;
        o.x = fmaf(d, W4.x, B4.x);
        o.y = fmaf(d, W4.y, B4.y);
        o.z = fmaf(d, W4.z, B4.z);
        o.w = fmaf(d, W4.w, B4.w);
        *(float4*)(eabase + (long)kk * DD + c4) = o;
    }
}

extern "C" void kernel_launch(void* const* d_in, const int* in_sizes, int n_in,
                              void* d_out, int out_size)
{
    const float2* locs = (const float2*)d_in[0];
    const float*  emb  = (const float*)d_in[1];
    const float*  Wv   = (const float*)d_in[2];
    const float*  bv   = (const float*)d_in[3];
    float* out = (float*)d_out;

    cudaFuncSetAttribute(edge_knn_kernel,
                         cudaFuncAttributeMaxDynamicSharedMemorySize, SMEM_BYTES);
    edge_knn_kernel<<<(BB * NN) / WARPS, THREADS, SMEM_BYTES>>>(locs, emb, Wv, bv, out);
}

// round 2
// speedup vs baseline: 1.4385x; 1.4385x over previous
#include <cuda_runtime.h>

// Problem constants (fixed by the dataset: B=32, N=1024, D=32, k = N//5 = 204)
#define BB      32
#define NN      1024
#define DD      32
#define KSEL    204
#define THREADS 256
#define WARPS   8

// Output layout (float32 concat of x, edge_index, edge_attr_emb)
#define X_ELEMS   (BB * NN * DD)            // 1,048,576
#define E_EDGES   ((long)BB * NN * KSEL)    // 6,684,672
#define EI_OFF    ((long)X_ELEMS)
#define EA_OFF    (EI_OFF + 2 * E_EDGES)    // 14,417,920

// Shared layout (bytes): slocs 8KB | cand 16KB | W/b 256B  (no dist buffer)
#define SMEM_BYTES (8192 + 16384 + 256)

__global__ __launch_bounds__(THREADS, 5)
void edge_knn_kernel(const float2* __restrict__ locs,
                     const float*  __restrict__ emb,
                     const float*  __restrict__ Wv,
                     const float*  __restrict__ bv,
                     float*        __restrict__ out)
{
    extern __shared__ unsigned char smem[];
    float2*             slocs = (float2*)smem;                       // [1024]
    unsigned long long* cand  = (unsigned long long*)(smem + 8192);  // [8][256]
    float*              sW    = (float*)(smem + 8192 + 16384);       // [32]
    float*              sB    = sW + 32;                             // [32]

    const int tid  = threadIdx.x;
    const int lane = tid & 31;
    const int w    = tid >> 5;
    const int cta  = blockIdx.x;          // 4096 CTAs
    const int batch = cta >> 7;           // 128 CTAs per batch instance
    const int i0    = (cta & 127) << 3;   // 8 rows per CTA (one per warp)

    // ---- x copy: out[0 : 1,048,576] = init_embeddings (4096*256 == X_ELEMS) ----
    out[cta * THREADS + tid] = emb[cta * THREADS + tid];

    // ---- stage batch locs + W/b into shared ----
    #pragma unroll
    for (int t = tid; t < NN; t += THREADS)
        slocs[t] = locs[batch * NN + t];
    if (tid < 32)      sW[tid]      = Wv[tid];
    else if (tid < 64) sB[tid - 32] = bv[tid - 32];
    __syncthreads();

    // ================= per-warp: one row i =================
    const int i = i0 + w;
    const float2 mi = slocs[i];
    unsigned long long* mycand = cand + w * 256;
    unsigned* hist = (unsigned*)mycand;   // alias: hist (1KB) lives inside cand (2KB)

    // zero hist
    #pragma unroll
    for (int r = 0; r < 8; ++r) hist[lane + 32 * r] = 0u;
    __syncwarp();

    // ---- pass 1: squared distances -> 256-bin histogram (uniform in sq) ----
    // sq = dx*dx + dy*dy with NO fma contraction (bit-exact vs reference).
    #pragma unroll 4
    for (int it = 0; it < NN / 32; ++it) {
        int j = it * 32 + lane;
        float2 lj = slocs[j];
        float dx = mi.x - lj.x;
        float dy = mi.y - lj.y;
        float sq = __fadd_rn(__fmul_rn(dx, dx), __fmul_rn(dy, dy));
        if (j != i) {
            int bin = (int)(__fmul_rn(sq, 128.0f));   // sq in [0,2] -> [0,256)
            bin = bin > 255 ? 255 : bin;
            atomicAdd(&hist[bin], 1u);
        }
    }
    __syncwarp();

    // ---- threshold bin: first bin with cumulative count >= KSEL ----
    unsigned h[8];
    int lsum = 0;
    #pragma unroll
    for (int r = 0; r < 8; ++r) { h[r] = hist[lane * 8 + r]; lsum += (int)h[r]; }
    int incl = lsum;
    #pragma unroll
    for (int o = 1; o < 32; o <<= 1) {
        int v = __shfl_up_sync(0xFFFFFFFFu, incl, o);
        if (lane >= o) incl += v;
    }
    int c  = incl - lsum;   // exclusive prefix of this lane's 8 bins
    int tb = 256;
    #pragma unroll
    for (int r = 0; r < 8; ++r) {
        c += (int)h[r];
        if (c >= KSEL && tb == 256) tb = lane * 8 + r;
    }
    #pragma unroll
    for (int o = 16; o; o >>= 1) {
        int v = __shfl_xor_sync(0xFFFFFFFFu, tb, o);
        tb = v < tb ? v : tb;
    }
    __syncwarp();   // hist reads done; cand region may now be overwritten
    // trunc(sq*128) <= tb  <=>  sq*128 < tb+1  (exact for tb+1 <= 256)
    const float thr = (float)(tb + 1);

    // ---- pass 2: recompute sq, compact candidates (sq*128 < thr) ----
    int cnt = 0;
    #pragma unroll 4
    for (int it = 0; it < NN / 32; ++it) {
        int j = it * 32 + lane;
        float2 lj = slocs[j];
        float dx = mi.x - lj.x;
        float dy = mi.y - lj.y;
        float sq = __fadd_rn(__fmul_rn(dx, dx), __fmul_rn(dy, dy));
        bool take = (j != i) && (__fmul_rn(sq, 128.0f) < thr);
        unsigned m = __ballot_sync(0xFFFFFFFFu, take);
        int pos = cnt + __popc(m & ((1u << lane) - 1u));
        if (take && pos < 256)
            mycand[pos] = ((unsigned long long)__float_as_uint(sq) << 32) | (unsigned)j;
        cnt += __popc(m);
    }
    int total = cnt > 256 ? 256 : cnt;    // >= KSEL by construction
    for (int p = total + lane; p < 256; p += 32)
        mycand[p] = ((unsigned long long)0x7F800000u << 32) | 0xFFFFFFFFu;  // +inf pad
    __syncwarp();

    // ---- load candidates, convert sq -> d (sqrt only on 256 survivors) ----
    unsigned long long key[8];
    #pragma unroll
    for (int r = 0; r < 8; ++r) {
        unsigned long long v = mycand[r * 32 + lane];
        float d = __fsqrt_rn(__uint_as_float((unsigned)(v >> 32)));  // sqrt(inf)=inf for pads
        key[r] = ((unsigned long long)__float_as_uint(d) << 32) | (unsigned)v;
    }

    // ---- register-resident bitonic sort of 256 u64 keys (8 per lane) ----
    #pragma unroll
    for (int kl = 1; kl <= 8; ++kl) {
        #pragma unroll
        for (int sl = kl - 1; sl >= 0; --sl) {
            #pragma unroll
            for (int r = 0; r < 8; ++r) {
                bool up;
                if (kl >= 6)      up = ((r & (1 << (kl - 5))) == 0);
                else if (kl == 5) up = ((r & 1) == 0);
                else              up = ((lane & (1 << kl)) == 0);
                if (sl >= 5) {
                    const int rs = 1 << (sl - 5);
                    if ((r & rs) == 0) {
                        const int r2 = r + rs;
                        unsigned long long a = key[r], b2 = key[r2];
                        bool sw = up ? (a > b2) : (a < b2);
                        key[r]  = sw ? b2 : a;
                        key[r2] = sw ? a  : b2;
                    }
                } else {
                    const int s = 1 << sl;
                    unsigned long long other = __shfl_xor_sync(0xFFFFFFFFu, key[r], s);
                    bool keepMin = (((lane & s) == 0) == up);
                    bool less = key[r] < other;
                    bool takeOther = (less != keepMin);
                    key[r] = takeOther ? other : key[r];
                }
            }
        }
    }

    // dump sorted keys back to shared for emission
    #pragma unroll
    for (int r = 0; r < 8; ++r) mycand[r * 32 + lane] = key[r];
    __syncwarp();

    // ---- emission ----
    const long  row  = (long)batch * NN + i;         // global node id
    float* o_src = out + EI_OFF;
    float* o_dst = o_src + E_EDGES;
    float* o_ea  = out + EA_OFF;
    const float srcv = (float)row;

    // edge_index (src row, dst row) as float32
    for (int kk = lane; kk < KSEL; kk += 32) {
        unsigned long long kv = mycand[kk];
        int j = (int)(unsigned)kv;
        o_src[row * KSEL + kk] = srcv;
        o_dst[row * KSEL + kk] = (float)((long)batch * NN + j);
    }

    // edge_attr_emb: out[e, c] = d * W[c] + b[c], float4-vectorized, coalesced
    const int eg = lane >> 3;          // which of 4 edges this lane covers
    const int c4 = (lane & 7) * 4;     // 4 embedding dims
    const float4 W4 = *(const float4*)(sW + c4);
    const float4 B4 = *(const float4*)(sB + c4);
    float* eabase = o_ea + row * (long)(KSEL * DD);
    #pragma unroll 4
    for (int kk0 = 0; kk0 < KSEL; kk0 += 4) {
        int kk = kk0 + eg;             // kk <= 203 always (204 = 4*51)
        unsigned dbits = *((unsigned*)&mycand[kk] + 1);   // high word = dist bits
        float d = __uint_as_float(dbits);
        float4 o;
        o.x = fmaf(d, W4.x, B4.x);
        o.y = fmaf(d, W4.y, B4.y);
        o.z = fmaf(d, W4.z, B4.z);
        o.w = fmaf(d, W4.w, B4.w);
        *(float4*)(eabase + (long)kk * DD + c4) = o;
    }
}

extern "C" void kernel_launch(void* const* d_in, const int* in_sizes, int n_in,
                              void* d_out, int out_size)
{
    const float2* locs = (const float2*)d_in[0];
    const float*  emb  = (const float*)d_in[1];
    const float*  Wv   = (const float*)d_in[2];
    const float*  bv   = (const float*)d_in[3];
    float* out = (float*)d_out;

    cudaFuncSetAttribute(edge_knn_kernel,
                         cudaFuncAttributeMaxDynamicSharedMemorySize, SMEM_BYTES);
    edge_knn_kernel<<<(BB * NN) / WARPS, THREADS, SMEM_BYTES>>>(locs, emb, Wv, bv, out);
}

// round 3
// speedup vs baseline: 1.5871x; 1.1033x over previous
#include <cuda_runtime.h>

// Problem constants (fixed by the dataset: B=32, N=1024, D=32, k = N//5 = 204)
#define BB      32
#define NN      1024
#define DD      32
#define KSEL    204
#define THREADS 256
#define WARPS   8

// Output layout (float32 concat of x, edge_index, edge_attr_emb)
#define X_ELEMS   (BB * NN * DD)            // 1,048,576
#define E_EDGES   ((long)BB * NN * KSEL)    // 6,684,672
#define EI_OFF    ((long)X_ELEMS)
#define EA_OFF    (EI_OFF + 2 * E_EDGES)    // 14,417,920

// Shared layout (bytes): slocs 8KB | per-warp scratch 8*2KB | W/b 256B
#define SMEM_BYTES (8192 + 16384 + 256)

__global__ __launch_bounds__(THREADS, 5)
void edge_knn_kernel(const float2* __restrict__ locs,
                     const float*  __restrict__ emb,
                     const float*  __restrict__ Wv,
                     const float*  __restrict__ bv,
                     float*        __restrict__ out)
{
    extern __shared__ unsigned char smem[];
    float2*             slocs   = (float2*)smem;                       // [1024]
    unsigned char*      scratch = smem + 8192;                         // 8 x 2KB
    float*              sW      = (float*)(smem + 8192 + 16384);       // [32]
    float*              sB      = sW + 32;                             // [32]

    const int tid  = threadIdx.x;
    const int lane = tid & 31;
    const int w    = tid >> 5;
    const int cta  = blockIdx.x;          // 4096 CTAs
    const int batch = cta >> 7;           // 128 CTAs per batch instance
    const int i0    = (cta & 127) << 3;   // 8 rows per CTA (one per warp)

    // ---- x copy: out[0 : 1,048,576] = init_embeddings (4096*256 == X_ELEMS) ----
    out[cta * THREADS + tid] = emb[cta * THREADS + tid];

    // ---- stage batch locs + W/b into shared ----
    #pragma unroll
    for (int t = tid; t < NN; t += THREADS)
        slocs[t] = locs[batch * NN + t];
    if (tid < 32)      sW[tid]      = Wv[tid];
    else if (tid < 64) sB[tid - 32] = bv[tid - 32];
    __syncthreads();

    // ================= per-warp: one row i =================
    const int i = i0 + w;
    const float2 mi = slocs[i];
    unsigned long long* mycand = (unsigned long long*)(scratch + w * 2048); // [256]
    unsigned* hist = (unsigned*)mycand;   // alias: hist (1KB) inside scratch
    float*    sd   = (float*)mycand;      // alias: padded dist floats (1152B)

    // zero hist
    #pragma unroll
    for (int r = 0; r < 8; ++r) hist[lane + 32 * r] = 0u;
    __syncwarp();

    // ---- pass 1: squared distances -> 256-bin histogram (uniform in sq) ----
    // sq = dx*dx + dy*dy with NO fma contraction (bit-exact vs reference).
    #pragma unroll 4
    for (int it = 0; it < NN / 32; ++it) {
        int j = it * 32 + lane;
        float2 lj = slocs[j];
        float dx = mi.x - lj.x;
        float dy = mi.y - lj.y;
        float sq = __fadd_rn(__fmul_rn(dx, dx), __fmul_rn(dy, dy));
        if (j != i) {
            int bin = (int)(__fmul_rn(sq, 128.0f));   // sq in [0,2] -> [0,256)
            bin = bin > 255 ? 255 : bin;
            atomicAdd(&hist[bin], 1u);
        }
    }
    __syncwarp();

    // ---- threshold bin: first bin with cumulative count >= KSEL ----
    unsigned h[8];
    int lsum = 0;
    #pragma unroll
    for (int r = 0; r < 8; ++r) { h[r] = hist[lane * 8 + r]; lsum += (int)h[r]; }
    int incl = lsum;
    #pragma unroll
    for (int o = 1; o < 32; o <<= 1) {
        int v = __shfl_up_sync(0xFFFFFFFFu, incl, o);
        if (lane >= o) incl += v;
    }
    int c  = incl - lsum;   // exclusive prefix of this lane's 8 bins
    int tb = 256;
    #pragma unroll
    for (int r = 0; r < 8; ++r) {
        c += (int)h[r];
        if (c >= KSEL && tb == 256) tb = lane * 8 + r;
    }
    #pragma unroll
    for (int o = 16; o; o >>= 1) {
        int v = __shfl_xor_sync(0xFFFFFFFFu, tb, o);
        tb = v < tb ? v : tb;
    }
    __syncwarp();   // hist reads done; scratch may now be overwritten
    // trunc(sq*128) <= tb  <=>  sq*128 < tb+1  (exact for tb+1 <= 256)
    const float thr = (float)(tb + 1);

    // ---- pass 2: recompute sq, compact candidates (sq*128 < thr) ----
    int cnt = 0;
    #pragma unroll 4
    for (int it = 0; it < NN / 32; ++it) {
        int j = it * 32 + lane;
        float2 lj = slocs[j];
        float dx = mi.x - lj.x;
        float dy = mi.y - lj.y;
        float sq = __fadd_rn(__fmul_rn(dx, dx), __fmul_rn(dy, dy));
        bool take = (j != i) && (__fmul_rn(sq, 128.0f) < thr);
        unsigned m = __ballot_sync(0xFFFFFFFFu, take);
        int pos = cnt + __popc(m & ((1u << lane) - 1u));
        if (take && pos < 256)
            mycand[pos] = ((unsigned long long)__float_as_uint(sq) << 32) | (unsigned)j;
        cnt += __popc(m);
    }
    int total = cnt > 256 ? 256 : cnt;    // >= KSEL by construction
    for (int p = total + lane; p < 256; p += 32)
        mycand[p] = ((unsigned long long)0x7F800000u << 32) | 0xFFFFFFFFu;  // +inf pad
    __syncwarp();

    // ---- load candidates (conflict-free), convert sq -> d on 256 survivors ----
    // Initial placement into the sorting network is arbitrary; network element
    // coordinates are e = lane*8 + r (bits 0-2 = r, bits 3-7 = lane) so that
    // strides 1,2,4 are register-local and only strides >=8 need SHFL.
    unsigned long long key[8];
    #pragma unroll
    for (int r = 0; r < 8; ++r) {
        unsigned long long v = mycand[r * 32 + lane];
        float d = __fsqrt_rn(__uint_as_float((unsigned)(v >> 32)));  // sqrt(inf)=inf
        key[r] = ((unsigned long long)__float_as_uint(d) << 32) | (unsigned)v;
    }
    __syncwarp();

    // ---- bitonic sort of 256 u64 keys, e = lane*8 + r ----
    #pragma unroll
    for (int kl = 1; kl <= 8; ++kl) {
        #pragma unroll
        for (int sl = kl - 1; sl >= 0; --sl) {
            if (sl >= 3) {
                const int ls = 1 << (sl - 3);          // lane stride
                const bool lowSide = ((lane & ls) == 0);
                // kl >= 4 here, so direction is lane-based
                const bool up = (((lane >> (kl - 3)) & 1) == 0);
                const bool keepMin = (lowSide == up);
                #pragma unroll
                for (int r = 0; r < 8; ++r) {
                    unsigned long long other = __shfl_xor_sync(0xFFFFFFFFu, key[r], ls);
                    bool less = key[r] < other;
                    key[r] = (less == keepMin) ? key[r] : other;
                }
            } else {
                const int s = 1 << sl;                 // register stride
                #pragma unroll
                for (int r = 0; r < 8; ++r) {
                    if ((r & s) == 0) {
                        const int r2 = r | s;
                        bool up = (kl < 3) ? (((r >> kl) & 1) == 0)
                                           : (((lane >> (kl - 3)) & 1) == 0);
                        unsigned long long a = key[r], b2 = key[r2];
                        bool sw = up ? (a > b2) : (a < b2);
                        key[r]  = sw ? b2 : a;
                        key[r2] = sw ? a  : b2;
                    }
                }
            }
        }
    }
    // lane L now holds sorted ranks L*8 .. L*8+7 in key[0..7]

    // ---- emission ----
    const long  row  = (long)batch * NN + i;         // global node id
    float* o_src = out + EI_OFF;
    float* o_dst = o_src + E_EDGES;
    float* o_ea  = out + EA_OFF;
    const float srcv = (float)row;
    const int   jbase = batch * NN;

    // edge_index straight from registers: lane covers kk = lane*8 .. lane*8+7
    {
        float dstf[8];
        #pragma unroll
        for (int r = 0; r < 8; ++r)
            dstf[r] = (float)(jbase + (int)(unsigned)key[r]);
        float* ps = o_src + row * KSEL + lane * 8;
        float* pd = o_dst + row * KSEL + lane * 8;
        const float4 s4 = make_float4(srcv, srcv, srcv, srcv);
        if (lane < 25) {
            __stcs((float4*)ps,     s4);
            __stcs((float4*)ps + 1, s4);
            __stcs((float4*)pd,     make_float4(dstf[0], dstf[1], dstf[2], dstf[3]));
            __stcs((float4*)pd + 1, make_float4(dstf[4], dstf[5], dstf[6], dstf[7]));
        } else if (lane == 25) {   // kk 200..203 only (KSEL = 204)
            __stcs((float4*)ps, s4);
            __stcs((float4*)pd, make_float4(dstf[0], dstf[1], dstf[2], dstf[3]));
        }
    }

    // dump dist floats to padded smem (stride 9 -> conflict-free)
    #pragma unroll
    for (int r = 0; r < 8; ++r)
        sd[lane * 9 + r] = __uint_as_float((unsigned)(key[r] >> 32));
    __syncwarp();

    // edge_attr_emb: out[e, c] = d * W[c] + b[c], float4-vectorized, coalesced
    const int eg = lane >> 3;          // which of 4 edges this lane covers
    const int c4 = (lane & 7) * 4;     // 4 embedding dims
    const float4 W4 = *(const float4*)(sW + c4);
    const float4 B4 = *(const float4*)(sB + c4);
    float* eabase = o_ea + row * (long)(KSEL * DD);
    #pragma unroll 4
    for (int kk0 = 0; kk0 < KSEL; kk0 += 4) {
        int kk = kk0 + eg;             // kk <= 203 always (204 = 4*51)
        float d = sd[(kk >> 3) * 9 + (kk & 7)];
        float4 o;
        o.x = fmaf(d, W4.x, B4.x);
        o.y = fmaf(d, W4.y, B4.y);
        o.z = fmaf(d, W4.z, B4.z);
        o.w = fmaf(d, W4.w, B4.w);
        __stcs((float4*)(eabase + (long)kk * DD + c4), o);
    }
}

extern "C" void kernel_launch(void* const* d_in, const int* in_sizes, int n_in,
                              void* d_out, int out_size)
{
    const float2* locs = (const float2*)d_in[0];
    const float*  emb  = (const float*)d_in[1];
    const float*  Wv   = (const float*)d_in[2];
    const float*  bv   = (const float*)d_in[3];
    float* out = (float*)d_out;

    cudaFuncSetAttribute(edge_knn_kernel,
                         cudaFuncAttributeMaxDynamicSharedMemorySize, SMEM_BYTES);
    edge_knn_kernel<<<(BB * NN) / WARPS, THREADS, SMEM_BYTES>>>(locs, emb, Wv, bv, out);
}